// round 8
// baseline (speedup 1.0000x reference)
#include <cuda_runtime.h>

// IntraLoss: loss = (1/N) * sum_n || features[n] - center[labels[n]] ||_2
// N=32768, C=1000, D=512. features f32 [N,D], labels int32 [N], center f32 [C,D].
//
// Persistent single-wave grid (148 SM x 8 blocks = 1184) with atomic work
// stealing over 1024 tickets of 32 consecutive rows each. Inside a ticket:
// R4's proven layout (8 warps x 4 rows, 8 lanes/row, batched float4 loads).
// Last block folds the partials and resets counters for graph replay.

#define NROWS    32768
#define NCLS     1000
#define DDIM     512
#define NBLK     1184          // 148 SMs * 8 blocks (occ 8 at 256 thr / 32 regs)
#define ROWS_PER_TICKET 32
#define NTICKETS (NROWS / ROWS_PER_TICKET)   // 1024

__device__ float g_partials[NBLK];
__device__ unsigned int g_counter = 0;
__device__ unsigned int g_ticket  = 0;

__global__ __launch_bounds__(256) void intra_loss_kernel(
    const float4* __restrict__ feats,    // [N, D/4]
    const int* __restrict__ labels,      // [N] int32
    const float4* __restrict__ center,   // [C, D/4]
    float* __restrict__ out)
{
    const int tid  = threadIdx.x;
    const int lane = tid & 31;
    const int wib  = tid >> 5;           // 0..7
    const int g    = lane >> 3;          // group 0..3
    const int l    = lane & 7;           // lane in group

    __shared__ unsigned int s_ticket;
    __shared__ float smem[8];
    __shared__ bool is_last;

    if (tid == 0) s_ticket = atomicAdd(&g_ticket, 1u);
    __syncthreads();

    float dsum = 0.0f;                   // per-thread (only group leaders nonzero)

    while (s_ticket < NTICKETS) {
        const int base = (int)s_ticket * ROWS_PER_TICKET;
        const int row  = base + (wib << 2) + g;    // warp covers 4 rows

        int lbl = labels[row];
        lbl = min(max(lbl, 0), NCLS - 1);

        const float4* fr = feats  + (size_t)row * (DDIM / 4) + l;
        const float4* cr = center + (size_t)lbl * (DDIM / 4) + l;

        float acc = 0.0f;
        #pragma unroll
        for (int i = 0; i < 16; i++) {
            float4 a = __ldcs(fr + i * 8);
            float4 b = __ldg(cr + i * 8);
            float dx = a.x - b.x;
            float dy = a.y - b.y;
            float dz = a.z - b.z;
            float dw = a.w - b.w;
            acc = fmaf(dx, dx, acc);
            acc = fmaf(dy, dy, acc);
            acc = fmaf(dz, dz, acc);
            acc = fmaf(dw, dw, acc);
        }

        // reduce within 8-lane group (4 rows in parallel)
        acc += __shfl_xor_sync(0xffffffffu, acc, 1);
        acc += __shfl_xor_sync(0xffffffffu, acc, 2);
        acc += __shfl_xor_sync(0xffffffffu, acc, 4);

        if (l == 0) dsum += sqrtf(acc);

        // grab next ticket
        __syncthreads();
        if (tid == 0) s_ticket = atomicAdd(&g_ticket, 1u);
        __syncthreads();
    }

    // fold the 4 group-leader sums within each warp
    dsum += __shfl_xor_sync(0xffffffffu, dsum, 8);
    dsum += __shfl_xor_sync(0xffffffffu, dsum, 16);

    if (lane == 0) smem[wib] = dsum;
    __syncthreads();

    if (tid == 0) {
        float s = 0.0f;
        #pragma unroll
        for (int i = 0; i < 8; i++) s += smem[i];
        g_partials[blockIdx.x] = s;
        __threadfence();
        unsigned int old = atomicAdd(&g_counter, 1u);
        is_last = (old == NBLK - 1);
    }
    __syncthreads();

    if (is_last) {
        float v = 0.0f;
        for (int i = tid; i < NBLK; i += 256)
            v += g_partials[i];

        #pragma unroll
        for (int s = 16; s > 0; s >>= 1)
            v += __shfl_xor_sync(0xffffffffu, v, s);

        __shared__ float smem2[8];
        if (lane == 0) smem2[wib] = v;
        __syncthreads();

        if (tid == 0) {
            float w = 0.0f;
            #pragma unroll
            for (int i = 0; i < 8; i++) w += smem2[i];
            out[0] = w * (1.0f / (float)NROWS);
            g_counter = 0;     // reset for next graph replay
            g_ticket  = 0;
        }
    }
}

extern "C" void kernel_launch(void* const* d_in, const int* in_sizes, int n_in,
                              void* d_out, int out_size)
{
    const float4* feats  = (const float4*)d_in[0];
    const int* labels    = (const int*)d_in[1];
    const float4* center = (const float4*)d_in[2];
    float* out           = (float*)d_out;

    intra_loss_kernel<<<NBLK, 256>>>(feats, labels, center, out);
}